// round 1
// baseline (speedup 1.0000x reference)
#include <cuda_runtime.h>
#include <cuda_bf16.h>

// EWRLS level filter, algebraically reduced:
//   lam = clip(sigmoid(logit_lambda[c]), 1e-4, 1-1e-4)
//   S_t = lam*S_{t-1} + x_t   (S_{-1} = 0)
//   Q_t = lam*Q_{t-1} + 1     (Q_{-1} = 0)
//   y_t = S_t / Q_t
// This is exactly equivalent to the reference Kalman-form recurrence:
//   P' = P/(lam+P) = K, prod(1-K) telescopes to lam^t * P_t.

#ifndef B_DIM
#define B_DIM 64
#endif
#define T_DIM 1024
#define C_DIM 512

static constexpr int U = 16;  // software pipeline depth (time steps per group)

__global__ __launch_bounds__(128, 8)
void ewrls_scan_kernel(const float* __restrict__ x,
                       const float* __restrict__ logit_lambda,
                       float* __restrict__ y) {
    const int g = blockIdx.x * blockDim.x + threadIdx.x;   // [0, B*C)
    const int c = g & (C_DIM - 1);
    const int b = g >> 9;                                   // g / C_DIM

    const size_t base = (size_t)b * T_DIM * C_DIM + c;
    const float* __restrict__ xp = x + base;
    float* __restrict__ yp = y + base;

    // lam per channel
    float l = __ldg(&logit_lambda[c]);
    float lam = 1.0f / (1.0f + __expf(-l));
    lam = fminf(fmaxf(lam, 1e-4f), 1.0f - 1e-4f);

    float S = 0.0f;
    float Q = 0.0f;

    // prefetch group 0
    float xv[U];
#pragma unroll
    for (int u = 0; u < U; u++) xv[u] = xp[(size_t)u * C_DIM];

#pragma unroll 1
    for (int t0 = 0; t0 < T_DIM - U; t0 += U) {
        // prefetch next group (independent of recurrence chain -> MLP=U)
        float xn[U];
        const float* __restrict__ xnp = xp + (size_t)(t0 + U) * C_DIM;
#pragma unroll
        for (int u = 0; u < U; u++) xn[u] = xnp[(size_t)u * C_DIM];

        // process current group
        float* __restrict__ yo = yp + (size_t)t0 * C_DIM;
#pragma unroll
        for (int u = 0; u < U; u++) {
            S = fmaf(lam, S, xv[u]);
            Q = fmaf(lam, Q, 1.0f);
            yo[(size_t)u * C_DIM] = __fdividef(S, Q);   // MUFU.RCP + FMUL, off critical path
        }

#pragma unroll
        for (int u = 0; u < U; u++) xv[u] = xn[u];
    }

    // last group (already loaded in xv)
    {
        float* __restrict__ yo = yp + (size_t)(T_DIM - U) * C_DIM;
#pragma unroll
        for (int u = 0; u < U; u++) {
            S = fmaf(lam, S, xv[u]);
            Q = fmaf(lam, Q, 1.0f);
            yo[(size_t)u * C_DIM] = __fdividef(S, Q);
        }
    }
}

extern "C" void kernel_launch(void* const* d_in, const int* in_sizes, int n_in,
                              void* d_out, int out_size) {
    // inputs: x [B*T*C] float32, logit_lambda [C] float32 (order-robust)
    const float* x;
    const float* logit_lambda;
    if (in_sizes[0] > in_sizes[1]) {
        x = (const float*)d_in[0];
        logit_lambda = (const float*)d_in[1];
    } else {
        x = (const float*)d_in[1];
        logit_lambda = (const float*)d_in[0];
    }
    float* y = (float*)d_out;

    const int total = B_DIM * C_DIM;      // 32768 threads, one per (b,c)
    const int threads = 128;
    const int blocks = total / threads;   // 256
    ewrls_scan_kernel<<<blocks, threads>>>(x, logit_lambda, y);
}